// round 7
// baseline (speedup 1.0000x reference)
#include <cuda_runtime.h>
#include <cstdint>

// ============================================================================
// FourierKARTLayer, 2-kernel version:
//   K1 (grid 448): blocks 0-255   -> angles[tok][q] = X0@WcT + b + w*t
//                  blocks 256-447 -> W2 fold (A,Bp -> A*cosB / A*sinB)
//   K2 (grid 512 = 256 token-tiles x 2 d-halves): sincos+harmonics -> F (smem),
//                  V[:, d-half] = F @ W2[:, d-half]   (disjoint writes, no atomics)
// ============================================================================

#define D_INF   256
#define D_OUTF  64
#define NQ      128
#define NK      6
#define NTOK    2048
#define TPB     256
#define TOKB    8
#define NFEAT   1536

__device__ float g_W2[NFEAT * D_OUTF];   // [f][d]
__device__ float g_ang[NTOK * NQ];       // [tok][q]

using u64 = unsigned long long;

__device__ __forceinline__ u64 pack2(float x, float y) {
    u64 r; asm("mov.b64 %0, {%1, %2};" : "=l"(r) : "f"(x), "f"(y)); return r;
}
__device__ __forceinline__ u64 fma2(u64 a, u64 b, u64 c) {
    u64 d; asm("fma.rn.f32x2 %0, %1, %2, %3;" : "=l"(d) : "l"(a), "l"(b), "l"(c)); return d;
}
__device__ __forceinline__ float2 unpack2(u64 a) {
    float2 f; asm("mov.b64 {%0, %1}, %2;" : "=f"(f.x), "=f"(f.y) : "l"(a)); return f;
}
__device__ __forceinline__ u64 add2(u64 a, u64 b) {
    u64 d; asm("add.rn.f32x2 %0, %1, %2;" : "=l"(d) : "l"(a), "l"(b)); return d;
}

// ----------------------------------------------------------------------------
// K1: angles (blocks 0-255) + W2 fold (blocks 256-447).
// dynamic smem 40KB: Xs [0,2048) | Wt [2048,10240) two 4096-float buffers.
// E (8KB = 1024 u64) aliases Wt buffer 0.
// ----------------------------------------------------------------------------
__global__ void __launch_bounds__(TPB) k1_kernel(
    const float* __restrict__ X0,
    const float* __restrict__ t,
    const float* __restrict__ Wc_w,
    const float* __restrict__ Wc_b,
    const float* __restrict__ w,
    const float* __restrict__ A,
    const float* __restrict__ Bp) {

    const int tid = threadIdx.x;

    if (blockIdx.x >= 256) {
        // ---- W2 fold: source-major, coalesced A/Bp reads ----------------
        int n = (blockIdx.x - 256) * TPB + tid;      // 0..49151
        int k  = n % NK;
        int dq = n / NK;
        int q  = dq & (NQ - 1);
        int d  = dq >> 7;
        float a  = __ldg(A + n);
        float bp = __ldg(Bp + n);
        float nr = rintf(bp * 0.15915494309189535f);
        float br = fmaf(nr, -6.283185307179586f, bp);
        float sb, cb;
        __sincosf(br, &sb, &cb);
        g_W2[(k * NQ + q) * D_OUTF + d]        = a * cb;   // sin-row coeff
        g_W2[((k + NK) * NQ + q) * D_OUTF + d] = a * sb;   // cos-row coeff
        return;
    }

    // ---- angles block ---------------------------------------------------
    extern __shared__ float smem[];
    float* Xs = smem;                 // [256 i][8 tok]
    float* Wt0 = smem + 2048;         // [32 i][128 q]
    float* Wt1 = smem + 6144;
    u64*   E   = (u64*)Wt0;           // [8 slot][128 q], aliases Wt0 at the end

    const int g0  = blockIdx.x * TOKB;
    const float tb = t[g0 >> 10];

    // load + transpose X (8 tok x 256 i)
    {
        int tok = tid >> 5;
        int seg = tid & 31;
        const float4* src = (const float4*)(X0 + (size_t)(g0 + tok) * D_INF + seg * 8);
        float4 v0 = src[0];
        float4 v1 = src[1];
        int i0 = seg * 8;
        Xs[(i0 + 0) * TOKB + tok] = v0.x;
        Xs[(i0 + 1) * TOKB + tok] = v0.y;
        Xs[(i0 + 2) * TOKB + tok] = v0.z;
        Xs[(i0 + 3) * TOKB + tok] = v0.w;
        Xs[(i0 + 4) * TOKB + tok] = v1.x;
        Xs[(i0 + 5) * TOKB + tok] = v1.y;
        Xs[(i0 + 6) * TOKB + tok] = v1.z;
        Xs[(i0 + 7) * TOKB + tok] = v1.w;
    }

    // Wc_w staging: chunk s = rows i in [s*32, s*32+32), transposed to Wt[i][q]
    const int sq   = tid >> 1;        // staging q
    const int half = tid & 1;         // 16 i's each
    const float* wsrc = Wc_w + sq * D_INF + half * 16;
    float4 r0, r1, r2, r3;

    #define LDCHUNK(s) do { \
        const float4* p_ = (const float4*)(wsrc + (s) * 32); \
        r0 = __ldg(p_); r1 = __ldg(p_ + 1); r2 = __ldg(p_ + 2); r3 = __ldg(p_ + 3); \
    } while (0)

    #define STCHUNK(Wt) do { \
        float* b_ = (Wt) + half * 16 * NQ + sq; \
        b_[0*NQ]=r0.x;  b_[1*NQ]=r0.y;  b_[2*NQ]=r0.z;  b_[3*NQ]=r0.w; \
        b_[4*NQ]=r1.x;  b_[5*NQ]=r1.y;  b_[6*NQ]=r1.z;  b_[7*NQ]=r1.w; \
        b_[8*NQ]=r2.x;  b_[9*NQ]=r2.y;  b_[10*NQ]=r2.z; b_[11*NQ]=r2.w; \
        b_[12*NQ]=r3.x; b_[13*NQ]=r3.y; b_[14*NQ]=r3.z; b_[15*NQ]=r3.w; \
    } while (0)

    LDCHUNK(0);
    STCHUNK(Wt0);

    const int ih = tid >> 7;          // 0/1: i_local halves
    const int q  = tid & (NQ - 1);
    u64 acc[4] = {0ULL, 0ULL, 0ULL, 0ULL};

    for (int s = 0; s < 8; s++) {
        if (s < 7) LDCHUNK(s + 1);
        __syncthreads();              // chunk s staged (and Xs on s=0)
        const float* Wt = (s & 1) ? Wt1 : Wt0;
        #pragma unroll 4
        for (int s2 = 0; s2 < 16; s2++) {
            int il = ih * 16 + s2;
            float wv = Wt[il * NQ + q];
            u64 wd = pack2(wv, wv);
            const float* xr = Xs + (s * 32 + il) * TOKB;
            ulonglong2 xa = *(const ulonglong2*)xr;
            ulonglong2 xb = *(const ulonglong2*)(xr + 4);
            acc[0] = fma2(xa.x, wd, acc[0]);
            acc[1] = fma2(xa.y, wd, acc[1]);
            acc[2] = fma2(xb.x, wd, acc[2]);
            acc[3] = fma2(xb.y, wd, acc[3]);
        }
        if (s < 7) STCHUNK((s & 1) ? Wt0 : Wt1);   // write other buffer
        __syncthreads();
    }
    #undef LDCHUNK
    #undef STCHUNK

    // exchange halves via E (aliases Wt0; all Wt reads done, sync'd above)
    #pragma unroll
    for (int p = 0; p < 4; p++)
        E[(p * 2 + ih) * NQ + q] = acc[p];
    __syncthreads();

    {
        const int th = tid >> 7;      // tokens th*4 .. th*4+3
        float init = fmaf(w[q], tb, Wc_b[q]);
        u64 bi = pack2(init, init);
        int p0 = th * 2;
        u64 s0 = add2(add2(E[(p0 * 2 + 0) * NQ + q], E[(p0 * 2 + 1) * NQ + q]), bi);
        u64 s1 = add2(add2(E[((p0 + 1) * 2 + 0) * NQ + q], E[((p0 + 1) * 2 + 1) * NQ + q]), bi);
        float2 a01 = unpack2(s0);
        float2 a23 = unpack2(s1);
        float* ap = g_ang + (size_t)(g0 + th * 4) * NQ + q;
        ap[0 * NQ] = a01.x;
        ap[1 * NQ] = a01.y;
        ap[2 * NQ] = a23.x;
        ap[3 * NQ] = a23.y;
    }
}

// ----------------------------------------------------------------------------
// K2: sincos + GEMM2 d-half. grid 512 = 256 tiles x 2 d-halves, 4 CTAs/SM.
// smem 48KB: Fs full [1536][8]; R (16KB) aliases Fs for the reduction.
// ----------------------------------------------------------------------------
__global__ void __launch_bounds__(TPB, 4) k2_kernel(float* __restrict__ V) {
    extern __shared__ float smem[];
    float* Fs = smem;                  // [1536 f][8 tok]
    u64*   R  = (u64*)smem;            // [16 fs][16 dg][8 slot]

    const int tid  = threadIdx.x;
    const int tile = blockIdx.x >> 1;
    const int h    = blockIdx.x & 1;   // d-half: d in [h*32, h*32+32)
    const int g0   = tile * TOKB;

    // ---- sincos + harmonic recurrence -> full F -------------------------
    {
        const int q  = tid & (NQ - 1);
        const int th = tid >> 7;        // tokens th*4 .. th*4+3
        const float* ap = g_ang + (size_t)(g0 + th * 4) * NQ + q;
        float ang[4] = {ap[0 * NQ], ap[1 * NQ], ap[2 * NQ], ap[3 * NQ]};

        float sv[4], cv[4], sk[4], ck[4];
        #pragma unroll
        for (int j = 0; j < 4; j++) {
            float nr = rintf(ang[j] * 0.15915494309189535f);
            float ar = fmaf(nr, -6.283185307179586f, ang[j]);
            __sincosf(ar, &sv[j], &cv[j]);
            sk[j] = sv[j]; ck[j] = cv[j];
        }
        float* base = Fs + q * TOKB + th * 4;
        #pragma unroll
        for (int k = 0; k < NK; k++) {
            *(float4*)(base + (k * NQ) * TOKB)        = make_float4(sk[0], sk[1], sk[2], sk[3]);
            *(float4*)(base + ((k + NK) * NQ) * TOKB) = make_float4(ck[0], ck[1], ck[2], ck[3]);
            #pragma unroll
            for (int j = 0; j < 4; j++) {
                float ns = fmaf(sk[j], cv[j], ck[j] * sv[j]);
                float nc = fmaf(ck[j], cv[j], -sk[j] * sv[j]);
                sk[j] = ns; ck[j] = nc;
            }
        }
    }
    __syncthreads();

    // ---- GEMM2 over all 1536 rows, 32 d-columns, tile 8tok x 2d ---------
    const int fs = tid >> 4;     // 0..15, f = j*16 + fs
    const int dg = tid & 15;     // d = h*32 + dg*2 + dd
    u64 acc[8];                  // [pair 4][dd 2]
    #pragma unroll
    for (int k = 0; k < 8; k++) acc[k] = 0ULL;

    const float* w2base = g_W2 + h * 32 + dg * 2;
    #pragma unroll 4
    for (int j = 0; j < NFEAT / 16; j++) {
        int f = j * 16 + fs;
        const float* frow = Fs + f * TOKB;
        ulonglong2 f01 = *(const ulonglong2*)frow;          // (t0,t1),(t2,t3)
        ulonglong2 f23 = *(const ulonglong2*)(frow + 4);    // (t4,t5),(t6,t7)
        float2 wv = __ldg((const float2*)(w2base + f * D_OUTF));
        u64 fp[4] = {f01.x, f01.y, f23.x, f23.y};
        u64 wd0 = pack2(wv.x, wv.x);
        u64 wd1 = pack2(wv.y, wv.y);
        #pragma unroll
        for (int p = 0; p < 4; p++) {
            acc[p * 2 + 0] = fma2(fp[p], wd0, acc[p * 2 + 0]);
            acc[p * 2 + 1] = fma2(fp[p], wd1, acc[p * 2 + 1]);
        }
    }

    // ---- Reduce over 16 f-slices (swizzled slots; R aliases Fs) ---------
    __syncthreads();
    #pragma unroll
    for (int p = 0; p < 4; p++)
        #pragma unroll
        for (int dd = 0; dd < 2; dd++)
            R[(fs * 16 + dg) * 8 + ((p * 2 + dd + 5 * dg) & 7)] = acc[p * 2 + dd];
    __syncthreads();

    if (tid < 128) {
        int p  = tid >> 5;             // token pair
        int dl = tid & 31;             // d_local
        int dg2 = dl >> 1;
        int dd  = dl & 1;
        int slot = (p * 2 + dd + 5 * dg2) & 7;
        u64 s = 0ULL;
        #pragma unroll
        for (int j = 0; j < 16; j++)
            s = add2(s, R[(j * 16 + dg2) * 8 + slot]);
        float2 v = unpack2(s);
        float* vp = V + (size_t)(g0 + 2 * p) * D_OUTF + h * 32 + dl;
        vp[0]      = v.x;
        vp[D_OUTF] = v.y;
    }
}

// ----------------------------------------------------------------------------
extern "C" void kernel_launch(void* const* d_in, const int* in_sizes, int n_in,
                              void* d_out, int out_size) {
    const float* X0   = (const float*)d_in[0];
    const float* t    = (const float*)d_in[1];
    const float* Wc_w = (const float*)d_in[2];
    const float* Wc_b = (const float*)d_in[3];
    const float* w    = (const float*)d_in[4];
    const float* A    = (const float*)d_in[5];
    const float* Bp   = (const float*)d_in[6];
    float* V = (float*)d_out;

    const int smem1 = 40960;           // Xs 8KB + 2x16KB Wt
    const int smem2 = 49152;           // Fs 48KB
    cudaFuncSetAttribute(k1_kernel, cudaFuncAttributeMaxDynamicSharedMemorySize, smem1);
    cudaFuncSetAttribute(k2_kernel, cudaFuncAttributeMaxDynamicSharedMemorySize, smem2);

    k1_kernel<<<448, TPB, smem1>>>(X0, t, Wc_w, Wc_b, w, A, Bp);
    k2_kernel<<<512, TPB, smem2>>>(V);
}

// round 8
// speedup vs baseline: 1.0616x; 1.0616x over previous
#include <cuda_runtime.h>
#include <cstdint>

// ============================================================================
// FourierKARTLayer, 3-kernel: prep -> angles -> K2 (sincos + GEMM2 d-half).
//   K2 grid 512 = 256 token-tiles(8) x 2 d-halves; full F in smem per block;
//   disjoint V writes (no atomics, no V zeroing).
// ============================================================================

#define D_INF   256
#define D_OUTF  64
#define NQ      128
#define NK      6
#define NTOK    2048
#define TPB     256
#define TOKB    8
#define NFEAT   1536

__device__ float g_WcT[D_INF * NQ];      // [i][q]
__device__ float g_W2[NFEAT * D_OUTF];   // [f][d]
__device__ float g_ang[NTOK * NQ];       // [tok][q]

using u64 = unsigned long long;

__device__ __forceinline__ u64 pack2(float x, float y) {
    u64 r; asm("mov.b64 %0, {%1, %2};" : "=l"(r) : "f"(x), "f"(y)); return r;
}
__device__ __forceinline__ u64 fma2(u64 a, u64 b, u64 c) {
    u64 d; asm("fma.rn.f32x2 %0, %1, %2, %3;" : "=l"(d) : "l"(a), "l"(b), "l"(c)); return d;
}
__device__ __forceinline__ float2 unpack2(u64 a) {
    float2 f; asm("mov.b64 {%0, %1}, %2;" : "=f"(f.x), "=f"(f.y) : "l"(a)); return f;
}
__device__ __forceinline__ u64 add2(u64 a, u64 b) {
    u64 d; asm("add.rn.f32x2 %0, %1, %2;" : "=l"(d) : "l"(a), "l"(b)); return d;
}

// ----------------------------------------------------------------------------
// K0: prep (W2 fold + WcT transpose). grid 512 x 256.
// ----------------------------------------------------------------------------
__global__ void prep_kernel(const float* __restrict__ Wc_w,
                            const float* __restrict__ A,
                            const float* __restrict__ Bp) {
    int n = blockIdx.x * blockDim.x + threadIdx.x;
    if (n < D_OUTF * NQ * NK) {                  // 49152, coalesced A/Bp reads
        int k  = n % NK;
        int dq = n / NK;
        int q  = dq & (NQ - 1);
        int d  = dq >> 7;
        float a  = __ldg(A + n);
        float bp = __ldg(Bp + n);
        float nr = rintf(bp * 0.15915494309189535f);
        float br = fmaf(nr, -6.283185307179586f, bp);
        float sb, cb;
        __sincosf(br, &sb, &cb);
        g_W2[(k * NQ + q) * D_OUTF + d]        = a * cb;   // sin-row coeff
        g_W2[((k + NK) * NQ + q) * D_OUTF + d] = a * sb;   // cos-row coeff
    }
    if (n < D_INF * NQ) {
        int q = n & (NQ - 1);
        int i = n >> 7;
        g_WcT[n] = Wc_w[q * D_INF + i];
    }
}

// ----------------------------------------------------------------------------
// K1: angles. grid 256 x 256 (8 tokens per block).  (unchanged from R5)
// ----------------------------------------------------------------------------
__global__ void __launch_bounds__(TPB) angles_kernel(
    const float* __restrict__ X0,
    const float* __restrict__ t,
    const float* __restrict__ Wc_b,
    const float* __restrict__ w) {

    __shared__ float Xs[D_INF * TOKB];     // [256 i][8 tok]
    __shared__ u64   E[4 * 2 * NQ];        // [pair][ih][q]

    const int tid = threadIdx.x;
    const int g0  = blockIdx.x * TOKB;
    const float tb = t[g0 >> 10];

    {
        int tok = tid >> 5;
        int seg = tid & 31;
        const float4* src = (const float4*)(X0 + (size_t)(g0 + tok) * D_INF + seg * 8);
        float4 v0 = src[0];
        float4 v1 = src[1];
        int i0 = seg * 8;
        Xs[(i0 + 0) * TOKB + tok] = v0.x;
        Xs[(i0 + 1) * TOKB + tok] = v0.y;
        Xs[(i0 + 2) * TOKB + tok] = v0.z;
        Xs[(i0 + 3) * TOKB + tok] = v0.w;
        Xs[(i0 + 4) * TOKB + tok] = v1.x;
        Xs[(i0 + 5) * TOKB + tok] = v1.y;
        Xs[(i0 + 6) * TOKB + tok] = v1.z;
        Xs[(i0 + 7) * TOKB + tok] = v1.w;
    }
    __syncthreads();

    {
        const int ih = tid >> 7;
        const int q  = tid & (NQ - 1);
        u64 acc[4] = {0ULL, 0ULL, 0ULL, 0ULL};
        #pragma unroll 8
        for (int s = 0; s < D_INF / 2; s++) {
            int i = ih * (D_INF / 2) + s;
            float wv = __ldg(g_WcT + i * NQ + q);
            u64 wd = pack2(wv, wv);
            ulonglong2 xa = *(const ulonglong2*)(Xs + i * TOKB);
            ulonglong2 xb = *(const ulonglong2*)(Xs + i * TOKB + 4);
            acc[0] = fma2(xa.x, wd, acc[0]);
            acc[1] = fma2(xa.y, wd, acc[1]);
            acc[2] = fma2(xb.x, wd, acc[2]);
            acc[3] = fma2(xb.y, wd, acc[3]);
        }
        #pragma unroll
        for (int p = 0; p < 4; p++)
            E[(p * 2 + ih) * NQ + q] = acc[p];
    }
    __syncthreads();

    {
        const int q  = tid & (NQ - 1);
        const int th = tid >> 7;
        float init = fmaf(w[q], tb, Wc_b[q]);
        u64 bi = pack2(init, init);
        int p0 = th * 2;
        u64 s0 = add2(add2(E[(p0 * 2 + 0) * NQ + q], E[(p0 * 2 + 1) * NQ + q]), bi);
        u64 s1 = add2(add2(E[((p0 + 1) * 2 + 0) * NQ + q], E[((p0 + 1) * 2 + 1) * NQ + q]), bi);
        float2 a01 = unpack2(s0);
        float2 a23 = unpack2(s1);
        float* ap = g_ang + (size_t)(g0 + th * 4) * NQ + q;
        ap[0 * NQ] = a01.x;
        ap[1 * NQ] = a01.y;
        ap[2 * NQ] = a23.x;
        ap[3 * NQ] = a23.y;
    }
}

// ----------------------------------------------------------------------------
// K2: sincos + GEMM2 d-half. grid 512 = 256 tiles x 2 d-halves, 4 CTAs/SM.
// smem 48KB: Fs [1536 f][8 tok]; R (32KB) aliases Fs for the reduction.
// ----------------------------------------------------------------------------
__global__ void __launch_bounds__(TPB, 4) k2_kernel(float* __restrict__ V) {
    extern __shared__ float smem[];
    float* Fs = smem;                  // [1536 f][8 tok]
    u64*   R  = (u64*)smem;            // [32 fs][128 col] swizzled

    const int tid  = threadIdx.x;
    const int tile = blockIdx.x >> 1;
    const int h    = blockIdx.x & 1;   // d-half: d in [h*32, h*32+32)
    const int g0   = tile * TOKB;

    // ---- sincos + harmonic recurrence -> full F -------------------------
    {
        const int q  = tid & (NQ - 1);
        const int th = tid >> 7;        // tokens th*4 .. th*4+3
        const float* ap = g_ang + (size_t)(g0 + th * 4) * NQ + q;
        float ang[4] = {ap[0 * NQ], ap[1 * NQ], ap[2 * NQ], ap[3 * NQ]};

        float sv[4], cv[4], sk[4], ck[4];
        #pragma unroll
        for (int j = 0; j < 4; j++) {
            float nr = rintf(ang[j] * 0.15915494309189535f);
            float ar = fmaf(nr, -6.283185307179586f, ang[j]);
            __sincosf(ar, &sv[j], &cv[j]);
            sk[j] = sv[j]; ck[j] = cv[j];
        }
        float* base = Fs + q * TOKB + th * 4;
        #pragma unroll
        for (int k = 0; k < NK; k++) {
            *(float4*)(base + (k * NQ) * TOKB)        = make_float4(sk[0], sk[1], sk[2], sk[3]);
            *(float4*)(base + ((k + NK) * NQ) * TOKB) = make_float4(ck[0], ck[1], ck[2], ck[3]);
            #pragma unroll
            for (int j = 0; j < 4; j++) {
                float ns = fmaf(sk[j], cv[j], ck[j] * sv[j]);
                float nc = fmaf(ck[j], cv[j], -sk[j] * sv[j]);
                sk[j] = ns; ck[j] = nc;
            }
        }
    }
    __syncthreads();

    // ---- GEMM2: thread = (fs 0..31, dg 0..7), tile 8 tok x 4 d ----------
    const int fs = tid >> 3;           // f = j*32 + fs
    const int dg = tid & 7;            // d = h*32 + dg*4 + dd
    u64 acc[16];                       // [pair 4][dd 4]
    #pragma unroll
    for (int k = 0; k < 16; k++) acc[k] = 0ULL;

    const float* w2base = g_W2 + h * 32 + dg * 4;
    #pragma unroll 4
    for (int j = 0; j < NFEAT / 32; j++) {
        int f = j * 32 + fs;
        const float* frow = Fs + f * TOKB;
        ulonglong2 f01 = *(const ulonglong2*)frow;          // (t0,t1),(t2,t3)
        ulonglong2 f23 = *(const ulonglong2*)(frow + 4);    // (t4,t5),(t6,t7)
        float4 wv = __ldg((const float4*)(w2base + f * D_OUTF));
        u64 fp[4] = {f01.x, f01.y, f23.x, f23.y};
        float wa[4] = {wv.x, wv.y, wv.z, wv.w};
        #pragma unroll
        for (int dd = 0; dd < 4; dd++) {
            u64 wd = pack2(wa[dd], wa[dd]);
            #pragma unroll
            for (int p = 0; p < 4; p++)
                acc[p * 4 + dd] = fma2(fp[p], wd, acc[p * 4 + dd]);
        }
    }

    // ---- Reduce over 32 f-slices (swizzled; R aliases Fs) ---------------
    __syncthreads();
    #pragma unroll
    for (int p = 0; p < 4; p++)
        #pragma unroll
        for (int dd = 0; dd < 4; dd++) {
            int col = (p * 32 + dg * 4 + dd + fs * 4) & 127;
            R[fs * 128 + col] = acc[p * 4 + dd];
        }
    __syncthreads();

    if (tid < 128) {
        int od = tid;                  // p = od>>5, c = od&31
        u64 s = 0ULL;
        #pragma unroll
        for (int j = 0; j < 32; j++)
            s = add2(s, R[j * 128 + ((od + j * 4) & 127)]);
        float2 v = unpack2(s);
        int p = od >> 5;
        int c = od & 31;
        float* vp = V + (size_t)(g0 + 2 * p) * D_OUTF + h * 32 + c;
        vp[0]      = v.x;
        vp[D_OUTF] = v.y;
    }
}

// ----------------------------------------------------------------------------
extern "C" void kernel_launch(void* const* d_in, const int* in_sizes, int n_in,
                              void* d_out, int out_size) {
    const float* X0   = (const float*)d_in[0];
    const float* t    = (const float*)d_in[1];
    const float* Wc_w = (const float*)d_in[2];
    const float* Wc_b = (const float*)d_in[3];
    const float* w    = (const float*)d_in[4];
    const float* A    = (const float*)d_in[5];
    const float* Bp   = (const float*)d_in[6];
    float* V = (float*)d_out;

    const int smem2 = 49152;           // Fs 48KB (R aliases)
    cudaFuncSetAttribute(k2_kernel, cudaFuncAttributeMaxDynamicSharedMemorySize, smem2);

    prep_kernel<<<512, 256>>>(Wc_w, A, Bp);
    angles_kernel<<<NTOK / TOKB, TPB>>>(X0, t, Wc_b, w);
    k2_kernel<<<2 * NTOK / TOKB, TPB, smem2>>>(V);
}